// round 4
// baseline (speedup 1.0000x reference)
#include <cuda_runtime.h>
#include <cuda_bf16.h>
#include <cstdint>
#include <math_constants.h>

// Problem: T=16384 tokens (S=4096*B=4), H=2048, E=64, top_k=2
#define NTOK 16384
#define HDIM 2048
#define NEXP 64
#define BM   128              // tokens per CTA
#define KC   16               // K per chunk (one mma k16)
#define NCH  (HDIM / KC)      // 128 chunks
#define XSTR 24               // smem row stride in bf16 elems (16 data + 8 pad = 48B)
#define TAU  5e-4f            // top-k ambiguity margin (>> split error ~1e-5)

// W preconverted to bf16 hi/lo (512KB total, device-global scratch)
__device__ __nv_bfloat16 g_whi[NEXP * HDIM];
__device__ __nv_bfloat16 g_wlo[NEXP * HDIM];
// ambiguous-token list for exact index refinement
__device__ int g_nflag;
__device__ int g_ftok[NTOK];

// ---------------- PTX helpers (all base sm_100 / sm_80-era) ----------------
__device__ __forceinline__ uint32_t smem_u32(const void* p) {
    uint32_t a;
    asm("{ .reg .u64 t; cvta.to.shared.u64 t, %1; cvt.u32.u64 %0, t; }" : "=r"(a) : "l"(p));
    return a;
}
__device__ __forceinline__ void ldsm4(uint32_t& r0, uint32_t& r1, uint32_t& r2, uint32_t& r3,
                                      uint32_t addr) {
    asm volatile("ldmatrix.sync.aligned.m8n8.x4.shared.b16 {%0,%1,%2,%3}, [%4];"
                 : "=r"(r0), "=r"(r1), "=r"(r2), "=r"(r3) : "r"(addr));
}
__device__ __forceinline__ void mma16816(float* c, const uint32_t* a, const uint32_t* b) {
    asm volatile(
        "mma.sync.aligned.m16n8k16.row.col.f32.bf16.bf16.f32 "
        "{%0,%1,%2,%3}, {%4,%5,%6,%7}, {%8,%9}, {%0,%1,%2,%3};"
        : "+f"(c[0]), "+f"(c[1]), "+f"(c[2]), "+f"(c[3])
        : "r"(a[0]), "r"(a[1]), "r"(a[2]), "r"(a[3]), "r"(b[0]), "r"(b[1]));
}
__device__ __forceinline__ void cp16(uint32_t saddr, const void* gaddr) {
    asm volatile("cp.async.ca.shared.global [%0], [%1], 16;" :: "r"(saddr), "l"(gaddr));
}
__device__ __forceinline__ void cp_commit() { asm volatile("cp.async.commit_group;"); }
__device__ __forceinline__ void cp_wait2()  { asm volatile("cp.async.wait_group 2;"); }
__device__ __forceinline__ void sts128(uint32_t a, uint32_t x, uint32_t y, uint32_t z, uint32_t w) {
    asm volatile("st.shared.v4.b32 [%0], {%1,%2,%3,%4};" :: "r"(a), "r"(x), "r"(y), "r"(z), "r"(w) : "memory");
}
// pack {a,b} -> bf16x2 word with a in the LOW half (memory-order first)
__device__ __forceinline__ uint32_t bfpack(float a, float b) {
    uint32_t r;
    asm("cvt.rn.bf16x2.f32 %0, %1, %2;" : "=r"(r) : "f"(b), "f"(a));
    return r;
}
__device__ __forceinline__ float bfround(float x) {
    return __bfloat162float(__float2bfloat16_rn(x));
}

// ------------------------- W preconversion kernel --------------------------
__global__ void wconv_kernel(const float* __restrict__ W) {
    const int i = blockIdx.x * blockDim.x + threadIdx.x;
    if (i < NEXP * HDIM) {
        const float w  = W[i];
        const float hi = bfround(w);
        g_whi[i] = __float2bfloat16_rn(hi);
        g_wlo[i] = __float2bfloat16_rn(w - hi);
    }
}

// ----------------------------- GEMM kernel ---------------------------------
// logits[T,64] = X[T,2048] . W[64,2048]^T via bf16 split, fp32 accum.
// 4 warps, warp = m32 x n64. X: reg-staged depth-2 -> smem double buffer.
// W: cp.async 3-buffer ring from preconverted bf16.
__global__ __launch_bounds__(128, 1)
void router_gemm_kernel(const float* __restrict__ X, float* __restrict__ logits) {
    __shared__ __align__(16) uint16_t Xhi[2][BM][XSTR];
    __shared__ __align__(16) uint16_t Xlo[2][BM][XSTR];
    __shared__ __align__(16) uint16_t Whi[3][NEXP][XSTR];
    __shared__ __align__(16) uint16_t Wlo[3][NEXP][XSTR];

    const int tid = threadIdx.x, wid = tid >> 5, lane = tid & 31;
    const int m0 = blockIdx.x * BM;

    // X staging: thread owns row `tid`, 16 fp32 (= one k16 chunk of that row)
    const float* xrow = X + (size_t)(m0 + tid) * HDIM;
    float4 xr[2][4];
    #pragma unroll
    for (int i = 0; i < 4; i++) xr[0][i] = ((const float4*)(xrow))[i];
    #pragma unroll
    for (int i = 0; i < 4; i++) xr[1][i] = ((const float4*)(xrow + KC))[i];

    // W cp.async mapping: thread -> row tid>>1, 16B segment tid&1 (hi and lo)
    const int wrow = tid >> 1, wseg = tid & 1;
    const __nv_bfloat16* gwh = g_whi + (size_t)wrow * HDIM + wseg * 8;
    const __nv_bfloat16* gwl = g_wlo + (size_t)wrow * HDIM + wseg * 8;
    {   // prologue: W chunks 0 and 1
        cp16(smem_u32(&Whi[0][wrow][wseg * 8]), gwh);
        cp16(smem_u32(&Wlo[0][wrow][wseg * 8]), gwl);
        cp_commit();
        cp16(smem_u32(&Whi[1][wrow][wseg * 8]), gwh + KC);
        cp16(smem_u32(&Wlo[1][wrow][wseg * 8]), gwl + KC);
        cp_commit();
    }

    float acc[2][8][4];
    #pragma unroll
    for (int mt = 0; mt < 2; mt++)
        #pragma unroll
        for (int nt = 0; nt < 8; nt++)
            #pragma unroll
            for (int q = 0; q < 4; q++) acc[mt][nt][q] = 0.f;

    // ldmatrix lane addressing (constant per thread)
    const int a_row  = wid * 32 + (lane & 15);
    const int a_koff = ((lane >> 4) & 1) * 8;
    const int b_nrow = (lane & 7) + ((lane >> 4) & 1) * 8;
    const int b_koff = ((lane >> 3) & 1) * 8;

    #pragma unroll 1
    for (int c = 0; c < NCH; c++) {
        const int xb = c & 1;
        const int wb = c % 3;

        // convert + STS chunk c (X) into buffer xb
        {
            const uint32_t xh = smem_u32(&Xhi[xb][tid][0]);
            const uint32_t xl = smem_u32(&Xlo[xb][tid][0]);
            uint32_t h[8], l[8];
            #pragma unroll
            for (int g = 0; g < 4; g++) {
                const float4 q = xr[xb][g];
                const float h0 = bfround(q.x), h1 = bfround(q.y);
                const float h2 = bfround(q.z), h3 = bfround(q.w);
                h[2 * g]     = bfpack(q.x, q.y);
                h[2 * g + 1] = bfpack(q.z, q.w);
                l[2 * g]     = bfpack(q.x - h0, q.y - h1);
                l[2 * g + 1] = bfpack(q.z - h2, q.w - h3);
            }
            sts128(xh,      h[0], h[1], h[2], h[3]);
            sts128(xh + 16, h[4], h[5], h[6], h[7]);
            sts128(xl,      l[0], l[1], l[2], l[3]);
            sts128(xl + 16, l[4], l[5], l[6], l[7]);
        }
        __syncthreads();

        // issue W chunk c+2 into ring slot (c+2)%3 (post-sync: slot is idle)
        if (c + 2 < NCH) {
            const int wb2 = (c + 2) % 3;
            cp16(smem_u32(&Whi[wb2][wrow][wseg * 8]), gwh + (c + 2) * KC);
            cp16(smem_u32(&Wlo[wb2][wrow][wseg * 8]), gwl + (c + 2) * KC);
        }
        cp_commit();          // always commit (empty at tail) -> constant wait count
        cp_wait2();           // W chunk c resident

        // prefetch X chunk c+2 into the register set just consumed
        if (c + 2 < NCH) {
            const float* xp = xrow + (c + 2) * KC;
            #pragma unroll
            for (int i = 0; i < 4; i++) xr[xb][i] = ((const float4*)xp)[i];
        }

        // ---- compute: B frags once, reused by both m16 tiles ----
        uint32_t bh[8][2], bl[8][2];
        #pragma unroll
        for (int p = 0; p < 4; p++) {
            ldsm4(bh[2 * p][0], bh[2 * p][1], bh[2 * p + 1][0], bh[2 * p + 1][1],
                  smem_u32(&Whi[wb][p * 16 + b_nrow][b_koff]));
            ldsm4(bl[2 * p][0], bl[2 * p][1], bl[2 * p + 1][0], bl[2 * p + 1][1],
                  smem_u32(&Wlo[wb][p * 16 + b_nrow][b_koff]));
        }
        #pragma unroll
        for (int mt = 0; mt < 2; mt++) {
            uint32_t ah[4], al[4];
            ldsm4(ah[0], ah[1], ah[2], ah[3], smem_u32(&Xhi[xb][a_row + mt * 16][a_koff]));
            ldsm4(al[0], al[1], al[2], al[3], smem_u32(&Xlo[xb][a_row + mt * 16][a_koff]));
            #pragma unroll
            for (int nt = 0; nt < 8; nt++) {
                mma16816(acc[mt][nt], ah, bh[nt]);   // hi*hi
                mma16816(acc[mt][nt], ah, bl[nt]);   // hi*lo
                mma16816(acc[mt][nt], al, bh[nt]);   // lo*hi
            }
        }
    }

    // epilogue: fragment stores (c0,c1 -> row g; c2,c3 -> row g+8)
    const int g = lane >> 2, t = lane & 3;
    #pragma unroll
    for (int mt = 0; mt < 2; mt++) {
        const int r0 = m0 + wid * 32 + mt * 16 + g;
        #pragma unroll
        for (int nt = 0; nt < 8; nt++) {
            const int col = nt * 8 + 2 * t;
            *(float2*)&logits[(size_t)r0 * NEXP + col]       = make_float2(acc[mt][nt][0], acc[mt][nt][1]);
            *(float2*)&logits[(size_t)(r0 + 8) * NEXP + col] = make_float2(acc[mt][nt][2], acc[mt][nt][3]);
        }
    }
}

// -------------------- softmax + top-2 + ambiguity flags --------------------
// One warp per token; lane owns logits[2*lane], logits[2*lane+1].
__global__ void softmax_topk_kernel(const float* __restrict__ logits,
                                    float* __restrict__ aff,
                                    float* __restrict__ idxf) {
    const int gw   = (int)((blockIdx.x * blockDim.x + threadIdx.x) >> 5);
    const int lane = threadIdx.x & 31;
    if (gw >= NTOK) return;

    const float2 v = *(const float2*)&logits[(size_t)gw * NEXP + 2 * lane];

    // top-1 with lowest-index tie-break
    float mv; int mi;
    if (v.y > v.x) { mv = v.y; mi = 2 * lane + 1; } else { mv = v.x; mi = 2 * lane; }
    #pragma unroll
    for (int off = 16; off; off >>= 1) {
        float ov = __shfl_xor_sync(0xffffffffu, mv, off);
        int   oi = __shfl_xor_sync(0xffffffffu, mi, off);
        if (ov > mv || (ov == mv && oi < mi)) { mv = ov; mi = oi; }
    }

    // softmax (fp32, max-subtracted)
    const float e0 = expf(v.x - mv);
    const float e1 = expf(v.y - mv);
    float s = e0 + e1;
    #pragma unroll
    for (int off = 16; off; off >>= 1) s += __shfl_xor_sync(0xffffffffu, s, off);
    const float inv = 1.0f / s;
    *(float2*)&aff[(size_t)gw * NEXP + 2 * lane] = make_float2(e0 * inv, e1 * inv);

    // top-2
    float v0 = (2 * lane     == mi) ? -CUDART_INF_F : v.x;
    float v1 = (2 * lane + 1 == mi) ? -CUDART_INF_F : v.y;
    float sv; int si;
    if (v1 > v0) { sv = v1; si = 2 * lane + 1; } else { sv = v0; si = 2 * lane; }
    #pragma unroll
    for (int off = 16; off; off >>= 1) {
        float ov = __shfl_xor_sync(0xffffffffu, sv, off);
        int   oi = __shfl_xor_sync(0xffffffffu, si, off);
        if (ov > sv || (ov == sv && oi < si)) { sv = ov; si = oi; }
    }

    // top-3 value only (for the gap2 test)
    if (2 * lane     == si) v0 = -CUDART_INF_F;
    if (2 * lane + 1 == si) v1 = -CUDART_INF_F;
    float tv = fmaxf(v0, v1);
    #pragma unroll
    for (int off = 16; off; off >>= 1)
        tv = fmaxf(tv, __shfl_xor_sync(0xffffffffu, tv, off));

    if (lane == 0) {
        idxf[2 * (size_t)gw + 0] = (float)mi;
        idxf[2 * (size_t)gw + 1] = (float)si;
        if (mv - sv < TAU || sv - tv < TAU)
            g_ftok[atomicAdd(&g_nflag, 1)] = gw;
    }
}

__global__ void reset_flags_kernel() { if (threadIdx.x == 0) g_nflag = 0; }

// ---------------- exact fp32 top-2 for ambiguous tokens --------------------
// One block (128 thr = 4 warps) per flagged token; warp w computes experts
// 16w..16w+15; thread 0 then rescans all 64 exact logits (ascending, strict >).
__global__ void refine_kernel(const float* __restrict__ X, const float* __restrict__ W,
                              float* __restrict__ idxf) {
    __shared__ float sl[NEXP];
    const int lane = threadIdx.x & 31, wid = threadIdx.x >> 5;
    const int n = g_nflag;

    for (int t = blockIdx.x; t < n; t += gridDim.x) {
        const int tok = g_ftok[t];
        const float* xrow = X + (size_t)tok * HDIM;
        for (int e = wid * 16; e < wid * 16 + 16; e++) {
            const float4* wr = (const float4*)(W + (size_t)e * HDIM);
            const float4* xp = (const float4*)xrow;
            float s = 0.f;
            for (int k = lane; k < HDIM / 4; k += 32) {
                const float4 a = xp[k], b = wr[k];
                s = fmaf(a.x, b.x, s); s = fmaf(a.y, b.y, s);
                s = fmaf(a.z, b.z, s); s = fmaf(a.w, b.w, s);
            }
            #pragma unroll
            for (int off = 16; off; off >>= 1) s += __shfl_xor_sync(0xffffffffu, s, off);
            if (lane == 0) sl[e] = s;
        }
        __syncthreads();
        if (threadIdx.x == 0) {
            float b1 = -CUDART_INF_F, b2 = -CUDART_INF_F;
            int i1 = 0, i2 = 0;
            for (int e = 0; e < NEXP; e++) {
                const float vv = sl[e];
                if (vv > b1)      { b2 = b1; i2 = i1; b1 = vv; i1 = e; }
                else if (vv > b2) { b2 = vv; i2 = e; }
            }
            idxf[2 * (size_t)tok + 0] = (float)i1;
            idxf[2 * (size_t)tok + 1] = (float)i2;
        }
        __syncthreads();
    }
}

// ---------------------------------------------------------------------------
// d_out (fp32): [0,T*E) logits | [T*E,2TE) affinities | [2TE, 2TE+2T) indices
// ---------------------------------------------------------------------------
extern "C" void kernel_launch(void* const* d_in, const int* in_sizes, int n_in,
                              void* d_out, int out_size) {
    (void)in_sizes; (void)n_in; (void)out_size;
    const float* X = (const float*)d_in[0];
    const float* W = (const float*)d_in[1];
    float* out    = (float*)d_out;
    float* logits = out;
    float* aff    = out + (size_t)NTOK * NEXP;
    float* idxf   = out + 2 * (size_t)NTOK * NEXP;

    wconv_kernel<<<(NEXP * HDIM + 255) / 256, 256>>>(W);
    reset_flags_kernel<<<1, 32>>>();
    router_gemm_kernel<<<NTOK / BM, 128>>>(X, logits);
    softmax_topk_kernel<<<NTOK / 8, 256>>>(logits, aff, idxf);
    refine_kernel<<<256, 128>>>(X, W, idxf);
}

// round 5
// speedup vs baseline: 1.2074x; 1.2074x over previous
#include <cuda_runtime.h>
#include <cuda_bf16.h>
#include <cstdint>
#include <math_constants.h>

// Problem: T=16384 tokens (S=4096*B=4), H=2048, E=64, top_k=2
#define NTOK 16384
#define HDIM 2048
#define NEXP 64
#define BM   128              // tokens per CTA
#define KC   32               // K per chunk (two mma k16 steps)
#define NCH  (HDIM / KC)      // 64 chunks
#define XSTR 40               // smem row stride in bf16 elems (32 data + 8 pad = 80B)
#define TAU  5e-4f            // top-k ambiguity margin (>> split error ~1e-5)

// dynamic smem layout (bytes)
#define SM_XHI   0
#define SM_XBUF  (BM * XSTR * 2)            // 10240 per buffer
#define SM_XLO   (2 * SM_XBUF)              // 20480
#define SM_WHI   (4 * SM_XBUF)              // 40960
#define SM_WSLOT (NEXP * XSTR * 2)          // 5120 per slot
#define SM_WLO   (SM_WHI + 3 * SM_WSLOT)    // 56320
#define SM_TOTAL (SM_WLO + 3 * SM_WSLOT)    // 71680

// W preconverted to bf16 hi/lo (512KB, device-global scratch)
__device__ __nv_bfloat16 g_whi[NEXP * HDIM];
__device__ __nv_bfloat16 g_wlo[NEXP * HDIM];
// ambiguous-token list for exact index refinement
__device__ int g_nflag;
__device__ int g_ftok[NTOK];

// ---------------- PTX helpers (base sm_100 / sm_80-era only) ---------------
__device__ __forceinline__ uint32_t smem_u32(const void* p) {
    uint32_t a;
    asm("{ .reg .u64 t; cvta.to.shared.u64 t, %1; cvt.u32.u64 %0, t; }" : "=r"(a) : "l"(p));
    return a;
}
__device__ __forceinline__ void ldsm4(uint32_t& r0, uint32_t& r1, uint32_t& r2, uint32_t& r3,
                                      uint32_t addr) {
    asm volatile("ldmatrix.sync.aligned.m8n8.x4.shared.b16 {%0,%1,%2,%3}, [%4];"
                 : "=r"(r0), "=r"(r1), "=r"(r2), "=r"(r3) : "r"(addr));
}
__device__ __forceinline__ void mma16816(float* c, const uint32_t* a, const uint32_t* b) {
    asm volatile(
        "mma.sync.aligned.m16n8k16.row.col.f32.bf16.bf16.f32 "
        "{%0,%1,%2,%3}, {%4,%5,%6,%7}, {%8,%9}, {%0,%1,%2,%3};"
        : "+f"(c[0]), "+f"(c[1]), "+f"(c[2]), "+f"(c[3])
        : "r"(a[0]), "r"(a[1]), "r"(a[2]), "r"(a[3]), "r"(b[0]), "r"(b[1]));
}
__device__ __forceinline__ void cp16(uint32_t saddr, const void* gaddr) {
    asm volatile("cp.async.ca.shared.global [%0], [%1], 16;" :: "r"(saddr), "l"(gaddr));
}
__device__ __forceinline__ void cp_commit() { asm volatile("cp.async.commit_group;"); }
__device__ __forceinline__ void cp_wait2()  { asm volatile("cp.async.wait_group 2;"); }
__device__ __forceinline__ void sts128(uint32_t a, uint32_t x, uint32_t y, uint32_t z, uint32_t w) {
    asm volatile("st.shared.v4.b32 [%0], {%1,%2,%3,%4};" :: "r"(a), "r"(x), "r"(y), "r"(z), "r"(w) : "memory");
}
// pack {a,b} -> bf16x2 word with a in the LOW half (memory-order first)
__device__ __forceinline__ uint32_t bfpack(float a, float b) {
    uint32_t r;
    asm("cvt.rn.bf16x2.f32 %0, %1, %2;" : "=r"(r) : "f"(b), "f"(a));
    return r;
}
__device__ __forceinline__ float bfround(float x) {
    return __bfloat162float(__float2bfloat16_rn(x));
}

// --------------- W preconversion (+ flag counter reset) --------------------
__global__ void wconv_kernel(const float* __restrict__ W) {
    const int i = blockIdx.x * blockDim.x + threadIdx.x;
    if (i == 0) g_nflag = 0;
    if (i < NEXP * HDIM) {
        const float w  = W[i];
        const float hi = bfround(w);
        g_whi[i] = __float2bfloat16_rn(hi);
        g_wlo[i] = __float2bfloat16_rn(w - hi);
    }
}

// ----------------------------- GEMM kernel ---------------------------------
// logits[T,64] = X[T,2048] . W[64,2048]^T via bf16 hi/lo split (3 products),
// fp32 accum. 8 warps, warp = m16 x n64 (2 warps/SMSP hides latency).
// X: reg-staged depth-2 -> smem double buffer. W: cp.async 3-slot ring from
// preconverted bf16. KC=32 halves the sync count vs KC=16.
__global__ __launch_bounds__(256, 1)
void router_gemm_kernel(const float* __restrict__ X, float* __restrict__ logits) {
    extern __shared__ __align__(16) char smem[];
    const uint32_t sbase = smem_u32(smem);

    const int tid = threadIdx.x, wid = tid >> 5, lane = tid & 31;
    const int m0 = blockIdx.x * BM;

    // X staging: thread owns row tid>>1, 16 fp32 (half tid&1 of the 32-wide chunk)
    const int xrow_i = tid >> 1, xhalf = tid & 1;
    const float* xrow = X + (size_t)(m0 + xrow_i) * HDIM + xhalf * 16;
    float4 xr[2][4];
    #pragma unroll
    for (int i = 0; i < 4; i++) xr[0][i] = ((const float4*)(xrow))[i];
    #pragma unroll
    for (int i = 0; i < 4; i++) xr[1][i] = ((const float4*)(xrow + KC))[i];

    // W cp.async mapping: thread -> row tid>>2, 16B segment tid&3
    const int wrow = tid >> 2, wseg = tid & 3;
    const __nv_bfloat16* gwh = g_whi + (size_t)wrow * HDIM + wseg * 8;
    const __nv_bfloat16* gwl = g_wlo + (size_t)wrow * HDIM + wseg * 8;
    const uint32_t w_sts = (uint32_t)(wrow * (XSTR * 2) + wseg * 16);
    {   // prologue: W chunks 0 and 1
        cp16(sbase + SM_WHI + 0 * SM_WSLOT + w_sts, gwh);
        cp16(sbase + SM_WLO + 0 * SM_WSLOT + w_sts, gwl);
        cp_commit();
        cp16(sbase + SM_WHI + 1 * SM_WSLOT + w_sts, gwh + KC);
        cp16(sbase + SM_WLO + 1 * SM_WSLOT + w_sts, gwl + KC);
        cp_commit();
    }

    float acc[8][4];
    #pragma unroll
    for (int nt = 0; nt < 8; nt++)
        #pragma unroll
        for (int q = 0; q < 4; q++) acc[nt][q] = 0.f;

    // ldmatrix lane addressing (bytes within a tile)
    const int a_row  = wid * 16 + (lane & 15);
    const int a_kb   = ((lane >> 4) & 1) * 16;              // 8 elems = 16B
    const int b_nrow = (lane & 7) + ((lane >> 4) & 1) * 8;
    const int b_kb   = ((lane >> 3) & 1) * 16;

    const uint32_t x_sts_base = (uint32_t)(xrow_i * (XSTR * 2) + xhalf * 32);

    #pragma unroll 1
    for (int c = 0; c < NCH; c++) {
        const int xb = c & 1;
        const int wb = c % 3;
        const uint32_t xhi_b = sbase + SM_XHI + xb * SM_XBUF;
        const uint32_t xlo_b = sbase + SM_XLO + xb * SM_XBUF;
        const uint32_t whi_b = sbase + SM_WHI + wb * SM_WSLOT;
        const uint32_t wlo_b = sbase + SM_WLO + wb * SM_WSLOT;

        // convert + STS chunk c (X) into buffer xb: 16 elems = 32B hi + 32B lo
        {
            uint32_t h[8], l[8];
            #pragma unroll
            for (int g = 0; g < 4; g++) {
                const float4 q = xr[xb][g];
                const float h0 = bfround(q.x), h1 = bfround(q.y);
                const float h2 = bfround(q.z), h3 = bfround(q.w);
                h[2 * g]     = bfpack(q.x, q.y);
                h[2 * g + 1] = bfpack(q.z, q.w);
                l[2 * g]     = bfpack(q.x - h0, q.y - h1);
                l[2 * g + 1] = bfpack(q.z - h2, q.w - h3);
            }
            sts128(xhi_b + x_sts_base,      h[0], h[1], h[2], h[3]);
            sts128(xhi_b + x_sts_base + 16, h[4], h[5], h[6], h[7]);
            sts128(xlo_b + x_sts_base,      l[0], l[1], l[2], l[3]);
            sts128(xlo_b + x_sts_base + 16, l[4], l[5], l[6], l[7]);
        }
        __syncthreads();

        // issue W chunk c+2 into ring slot (c+2)%3 (idle since iter c-1's sync)
        if (c + 2 < NCH) {
            const int wb2 = (c + 2) % 3;
            cp16(sbase + SM_WHI + wb2 * SM_WSLOT + w_sts, gwh + (c + 2) * KC);
            cp16(sbase + SM_WLO + wb2 * SM_WSLOT + w_sts, gwl + (c + 2) * KC);
        }
        cp_commit();          // constant-rate commits -> constant wait count
        cp_wait2();           // W chunk c resident

        // prefetch X chunk c+2 into the register set just consumed
        if (c + 2 < NCH) {
            const float* xp = xrow + (c + 2) * KC;
            #pragma unroll
            for (int i = 0; i < 4; i++) xr[xb][i] = ((const float4*)xp)[i];
        }

        // ---- compute: two k16 steps ----
        #pragma unroll
        for (int ks = 0; ks < 2; ks++) {
            const uint32_t kb = (uint32_t)(ks * 32);  // 16 elems = 32B
            uint32_t bh[8][2], bl[8][2];
            #pragma unroll
            for (int p = 0; p < 4; p++) {
                const uint32_t boff = (uint32_t)((p * 16 + b_nrow) * (XSTR * 2)) + kb + b_kb;
                ldsm4(bh[2 * p][0], bh[2 * p][1], bh[2 * p + 1][0], bh[2 * p + 1][1], whi_b + boff);
                ldsm4(bl[2 * p][0], bl[2 * p][1], bl[2 * p + 1][0], bl[2 * p + 1][1], wlo_b + boff);
            }
            uint32_t ah[4], al[4];
            const uint32_t aoff = (uint32_t)(a_row * (XSTR * 2)) + kb + a_kb;
            ldsm4(ah[0], ah[1], ah[2], ah[3], xhi_b + aoff);
            ldsm4(al[0], al[1], al[2], al[3], xlo_b + aoff);
            #pragma unroll
            for (int nt = 0; nt < 8; nt++) {
                mma16816(acc[nt], ah, bh[nt]);   // hi*hi
                mma16816(acc[nt], ah, bl[nt]);   // hi*lo
                mma16816(acc[nt], al, bh[nt]);   // lo*hi
            }
        }
    }

    // epilogue: fragment stores (c0,c1 -> row g; c2,c3 -> row g+8)
    const int g = lane >> 2, t = lane & 3;
    const int r0 = m0 + wid * 16 + g;
    #pragma unroll
    for (int nt = 0; nt < 8; nt++) {
        const int col = nt * 8 + 2 * t;
        *(float2*)&logits[(size_t)r0 * NEXP + col]       = make_float2(acc[nt][0], acc[nt][1]);
        *(float2*)&logits[(size_t)(r0 + 8) * NEXP + col] = make_float2(acc[nt][2], acc[nt][3]);
    }
}

// -------------------- softmax + top-2 + ambiguity flags --------------------
// One warp per token; lane owns logits[2*lane], logits[2*lane+1].
__global__ void softmax_topk_kernel(const float* __restrict__ logits,
                                    float* __restrict__ aff,
                                    float* __restrict__ idxf) {
    const int gw   = (int)((blockIdx.x * blockDim.x + threadIdx.x) >> 5);
    const int lane = threadIdx.x & 31;
    if (gw >= NTOK) return;

    const float2 v = *(const float2*)&logits[(size_t)gw * NEXP + 2 * lane];

    // top-1 with lowest-index tie-break
    float mv; int mi;
    if (v.y > v.x) { mv = v.y; mi = 2 * lane + 1; } else { mv = v.x; mi = 2 * lane; }
    #pragma unroll
    for (int off = 16; off; off >>= 1) {
        float ov = __shfl_xor_sync(0xffffffffu, mv, off);
        int   oi = __shfl_xor_sync(0xffffffffu, mi, off);
        if (ov > mv || (ov == mv && oi < mi)) { mv = ov; mi = oi; }
    }

    // softmax (fp32, max-subtracted)
    const float e0 = expf(v.x - mv);
    const float e1 = expf(v.y - mv);
    float s = e0 + e1;
    #pragma unroll
    for (int off = 16; off; off >>= 1) s += __shfl_xor_sync(0xffffffffu, s, off);
    const float inv = 1.0f / s;
    *(float2*)&aff[(size_t)gw * NEXP + 2 * lane] = make_float2(e0 * inv, e1 * inv);

    // top-2
    float v0 = (2 * lane     == mi) ? -CUDART_INF_F : v.x;
    float v1 = (2 * lane + 1 == mi) ? -CUDART_INF_F : v.y;
    float sv; int si;
    if (v1 > v0) { sv = v1; si = 2 * lane + 1; } else { sv = v0; si = 2 * lane; }
    #pragma unroll
    for (int off = 16; off; off >>= 1) {
        float ov = __shfl_xor_sync(0xffffffffu, sv, off);
        int   oi = __shfl_xor_sync(0xffffffffu, si, off);
        if (ov > sv || (ov == sv && oi < si)) { sv = ov; si = oi; }
    }

    // top-3 value only (for the gap2 test)
    if (2 * lane     == si) v0 = -CUDART_INF_F;
    if (2 * lane + 1 == si) v1 = -CUDART_INF_F;
    float tv = fmaxf(v0, v1);
    #pragma unroll
    for (int off = 16; off; off >>= 1)
        tv = fmaxf(tv, __shfl_xor_sync(0xffffffffu, tv, off));

    if (lane == 0) {
        idxf[2 * (size_t)gw + 0] = (float)mi;
        idxf[2 * (size_t)gw + 1] = (float)si;
        if (mv - sv < TAU || sv - tv < TAU)
            g_ftok[atomicAdd(&g_nflag, 1)] = gw;
    }
}

// ---------------- exact fp32 top-2 for ambiguous tokens --------------------
__global__ void refine_kernel(const float* __restrict__ X, const float* __restrict__ W,
                              float* __restrict__ idxf) {
    __shared__ float sl[NEXP];
    const int lane = threadIdx.x & 31, wid = threadIdx.x >> 5;
    const int n = g_nflag;

    for (int t = blockIdx.x; t < n; t += gridDim.x) {
        const int tok = g_ftok[t];
        const float* xrow = X + (size_t)tok * HDIM;
        for (int e = wid * 16; e < wid * 16 + 16; e++) {
            const float4* wr = (const float4*)(W + (size_t)e * HDIM);
            const float4* xp = (const float4*)xrow;
            float s = 0.f;
            for (int k = lane; k < HDIM / 4; k += 32) {
                const float4 a = xp[k], b = wr[k];
                s = fmaf(a.x, b.x, s); s = fmaf(a.y, b.y, s);
                s = fmaf(a.z, b.z, s); s = fmaf(a.w, b.w, s);
            }
            #pragma unroll
            for (int off = 16; off; off >>= 1) s += __shfl_xor_sync(0xffffffffu, s, off);
            if (lane == 0) sl[e] = s;
        }
        __syncthreads();
        if (threadIdx.x == 0) {
            float b1 = -CUDART_INF_F, b2 = -CUDART_INF_F;
            int i1 = 0, i2 = 0;
            for (int e = 0; e < NEXP; e++) {
                const float vv = sl[e];
                if (vv > b1)      { b2 = b1; i2 = i1; b1 = vv; i1 = e; }
                else if (vv > b2) { b2 = vv; i2 = e; }
            }
            idxf[2 * (size_t)tok + 0] = (float)i1;
            idxf[2 * (size_t)tok + 1] = (float)i2;
        }
        __syncthreads();
    }
}

// ---------------------------------------------------------------------------
// d_out (fp32): [0,T*E) logits | [T*E,2TE) affinities | [2TE, 2TE+2T) indices
// ---------------------------------------------------------------------------
extern "C" void kernel_launch(void* const* d_in, const int* in_sizes, int n_in,
                              void* d_out, int out_size) {
    (void)in_sizes; (void)n_in; (void)out_size;
    const float* X = (const float*)d_in[0];
    const float* W = (const float*)d_in[1];
    float* out    = (float*)d_out;
    float* logits = out;
    float* aff    = out + (size_t)NTOK * NEXP;
    float* idxf   = out + 2 * (size_t)NTOK * NEXP;

    static int smem_set = 0;
    if (!smem_set) {
        cudaFuncSetAttribute(router_gemm_kernel,
                             cudaFuncAttributeMaxDynamicSharedMemorySize, SM_TOTAL);
        smem_set = 1;
    }

    wconv_kernel<<<(NEXP * HDIM + 255) / 256, 256>>>(W);
    router_gemm_kernel<<<NTOK / BM, 256, SM_TOTAL>>>(X, logits);
    softmax_topk_kernel<<<NTOK / 8, 256>>>(logits, aff, idxf);
    refine_kernel<<<256, 128>>>(X, W, idxf);
}

// round 7
// speedup vs baseline: 1.6557x; 1.3713x over previous
#include <cuda_runtime.h>
#include <cuda_bf16.h>
#include <cstdint>
#include <math_constants.h>

// Problem: T=16384 tokens (S=4096*B=4), H=2048, E=64, top_k=2
#define NTOK 16384
#define HDIM 2048
#define NEXP 64
#define BM   64               // tokens per CTA (2 CTAs/SM)
#define KC   32               // K per chunk (two mma k16 steps)
#define NCH  (HDIM / KC)      // 64 chunks
#define XSTR 40               // smem row stride in bf16 elems (32 data + 8 pad = 80B)
#define TAU  5e-4f            // top-k ambiguity margin (>> split error ~1e-5)

// dynamic smem layout (bytes): tile = 64 rows x 80B = 5120
#define SM_TILE  (BM * XSTR * 2)            // 5120
#define SM_XHI   0                          // 2 buffers
#define SM_XLO   (2 * SM_TILE)              // 10240
#define SM_WHI   (4 * SM_TILE)              // 20480, 3 slots
#define SM_WLO   (SM_WHI + 3 * SM_TILE)     // 35840
#define SM_TOTAL (SM_WLO + 3 * SM_TILE)     // 51200

// W preconverted to bf16 hi/lo (512KB, device-global scratch)
__device__ __nv_bfloat16 g_whi[NEXP * HDIM];
__device__ __nv_bfloat16 g_wlo[NEXP * HDIM];
// ambiguous-token list for exact index refinement
__device__ int g_nflag;
__device__ int g_ftok[NTOK];

// ---------------- PTX helpers (base sm_100 / sm_80-era only) ---------------
__device__ __forceinline__ uint32_t smem_u32(const void* p) {
    uint32_t a;
    asm("{ .reg .u64 t; cvta.to.shared.u64 t, %1; cvt.u32.u64 %0, t; }" : "=r"(a) : "l"(p));
    return a;
}
__device__ __forceinline__ void ldsm4(uint32_t& r0, uint32_t& r1, uint32_t& r2, uint32_t& r3,
                                      uint32_t addr) {
    asm volatile("ldmatrix.sync.aligned.m8n8.x4.shared.b16 {%0,%1,%2,%3}, [%4];"
                 : "=r"(r0), "=r"(r1), "=r"(r2), "=r"(r3) : "r"(addr));
}
__device__ __forceinline__ void mma16816(float* c, const uint32_t* a, const uint32_t* b) {
    asm volatile(
        "mma.sync.aligned.m16n8k16.row.col.f32.bf16.bf16.f32 "
        "{%0,%1,%2,%3}, {%4,%5,%6,%7}, {%8,%9}, {%0,%1,%2,%3};"
        : "+f"(c[0]), "+f"(c[1]), "+f"(c[2]), "+f"(c[3])
        : "r"(a[0]), "r"(a[1]), "r"(a[2]), "r"(a[3]), "r"(b[0]), "r"(b[1]));
}
__device__ __forceinline__ void cp16(uint32_t saddr, const void* gaddr) {
    asm volatile("cp.async.ca.shared.global [%0], [%1], 16;" :: "r"(saddr), "l"(gaddr));
}
__device__ __forceinline__ void cp_commit() { asm volatile("cp.async.commit_group;"); }
__device__ __forceinline__ void cp_wait2()  { asm volatile("cp.async.wait_group 2;"); }
__device__ __forceinline__ void sts128(uint32_t a, uint32_t x, uint32_t y, uint32_t z, uint32_t w) {
    asm volatile("st.shared.v4.b32 [%0], {%1,%2,%3,%4};" :: "r"(a), "r"(x), "r"(y), "r"(z), "r"(w) : "memory");
}
// pack {a,b} -> bf16x2 word with a in the LOW half (memory-order first)
__device__ __forceinline__ uint32_t bfpack(float a, float b) {
    uint32_t r;
    asm("cvt.rn.bf16x2.f32 %0, %1, %2;" : "=r"(r) : "f"(b), "f"(a));
    return r;
}
__device__ __forceinline__ float bfround(float x) {
    return __bfloat162float(__float2bfloat16_rn(x));
}

// --------------- W preconversion (+ flag counter reset) --------------------
__global__ void wconv_kernel(const float* __restrict__ W) {
    const int i = blockIdx.x * blockDim.x + threadIdx.x;
    if (i == 0) g_nflag = 0;
    if (i < NEXP * HDIM) {
        const float w  = W[i];
        const float hi = bfround(w);
        g_whi[i] = __float2bfloat16_rn(hi);
        g_wlo[i] = __float2bfloat16_rn(w - hi);
    }
}

// ------------------- fused GEMM + softmax + top-k kernel -------------------
// logits[T,64] = X[T,2048] . W[64,2048]^T via bf16 hi/lo split (3 products),
// fp32 accum. 4 warps, warp = m16 x n64; BM=64 -> grid 256 -> 2 CTAs/SM so
// independent CTAs hide each other's sync/LDG bubbles.
// Epilogue: each warp holds complete expert rows (row = lane quad) -> softmax
// + top-2 + ambiguity flags via quad shuffles; no separate softmax kernel.
__global__ __launch_bounds__(128, 2)
void router_gemm_kernel(const float* __restrict__ X, float* __restrict__ logits,
                        float* __restrict__ aff, float* __restrict__ idxf) {
    extern __shared__ __align__(16) char smem[];
    const uint32_t sbase = smem_u32(smem);

    const int tid = threadIdx.x, wid = tid >> 5, lane = tid & 31;
    const int m0 = blockIdx.x * BM;

    // X staging: thread owns row tid>>1, 16 fp32 (half tid&1 of 32-wide chunk)
    const int xrow_i = tid >> 1, xhalf = tid & 1;
    const float* xrow = X + (size_t)(m0 + xrow_i) * HDIM + xhalf * 16;
    float4 xr[2][4];
    #pragma unroll
    for (int i = 0; i < 4; i++) xr[0][i] = ((const float4*)(xrow))[i];
    #pragma unroll
    for (int i = 0; i < 4; i++) xr[1][i] = ((const float4*)(xrow + KC))[i];

    // W cp.async: thread -> row tid>>1, 32B half tid&1 (2x cp16 per matrix)
    const int wrow = tid >> 1, whalf = tid & 1;
    const __nv_bfloat16* gwh = g_whi + (size_t)wrow * HDIM + whalf * 16;
    const __nv_bfloat16* gwl = g_wlo + (size_t)wrow * HDIM + whalf * 16;
    const uint32_t w_sts = (uint32_t)(wrow * (XSTR * 2) + whalf * 32);
    {   // prologue: W chunks 0 and 1
        cp16(sbase + SM_WHI + 0 * SM_TILE + w_sts,      gwh);
        cp16(sbase + SM_WHI + 0 * SM_TILE + w_sts + 16, gwh + 8);
        cp16(sbase + SM_WLO + 0 * SM_TILE + w_sts,      gwl);
        cp16(sbase + SM_WLO + 0 * SM_TILE + w_sts + 16, gwl + 8);
        cp_commit();
        cp16(sbase + SM_WHI + 1 * SM_TILE + w_sts,      gwh + KC);
        cp16(sbase + SM_WHI + 1 * SM_TILE + w_sts + 16, gwh + KC + 8);
        cp16(sbase + SM_WLO + 1 * SM_TILE + w_sts,      gwl + KC);
        cp16(sbase + SM_WLO + 1 * SM_TILE + w_sts + 16, gwl + KC + 8);
        cp_commit();
    }

    float acc[8][4];
    #pragma unroll
    for (int nt = 0; nt < 8; nt++)
        #pragma unroll
        for (int q = 0; q < 4; q++) acc[nt][q] = 0.f;

    // ldmatrix lane addressing (byte offsets within a tile)
    const int a_row  = wid * 16 + (lane & 15);
    const int a_kb   = ((lane >> 4) & 1) * 16;
    const int b_nrow = (lane & 7) + ((lane >> 4) & 1) * 8;
    const int b_kb   = ((lane >> 3) & 1) * 16;
    const uint32_t x_sts_base = (uint32_t)(xrow_i * (XSTR * 2) + xhalf * 32);

    #pragma unroll 1
    for (int c = 0; c < NCH; c++) {
        const int xb = c & 1;
        const int wb = c % 3;
        const uint32_t xhi_b = sbase + SM_XHI + xb * SM_TILE;
        const uint32_t xlo_b = sbase + SM_XLO + xb * SM_TILE;
        const uint32_t whi_b = sbase + SM_WHI + wb * SM_TILE;
        const uint32_t wlo_b = sbase + SM_WLO + wb * SM_TILE;

        // convert + STS chunk c (X) into buffer xb
        {
            uint32_t h[8], l[8];
            #pragma unroll
            for (int g = 0; g < 4; g++) {
                const float4 q = xr[xb][g];
                const float h0 = bfround(q.x), h1 = bfround(q.y);
                const float h2 = bfround(q.z), h3 = bfround(q.w);
                h[2 * g]     = bfpack(q.x, q.y);
                h[2 * g + 1] = bfpack(q.z, q.w);
                l[2 * g]     = bfpack(q.x - h0, q.y - h1);
                l[2 * g + 1] = bfpack(q.z - h2, q.w - h3);
            }
            sts128(xhi_b + x_sts_base,      h[0], h[1], h[2], h[3]);
            sts128(xhi_b + x_sts_base + 16, h[4], h[5], h[6], h[7]);
            sts128(xlo_b + x_sts_base,      l[0], l[1], l[2], l[3]);
            sts128(xlo_b + x_sts_base + 16, l[4], l[5], l[6], l[7]);
        }
        __syncthreads();

        // issue W chunk c+2 into ring slot (c+2)%3 (idle since iter c-1's sync)
        if (c + 2 < NCH) {
            const int wb2 = (c + 2) % 3;
            const int ko = (c + 2) * KC;
            cp16(sbase + SM_WHI + wb2 * SM_TILE + w_sts,      gwh + ko);
            cp16(sbase + SM_WHI + wb2 * SM_TILE + w_sts + 16, gwh + ko + 8);
            cp16(sbase + SM_WLO + wb2 * SM_TILE + w_sts,      gwl + ko);
            cp16(sbase + SM_WLO + wb2 * SM_TILE + w_sts + 16, gwl + ko + 8);
        }
        cp_commit();          // constant-rate commits -> constant wait count
        cp_wait2();           // W chunk c resident

        // prefetch X chunk c+2 into the register set just consumed
        if (c + 2 < NCH) {
            const float* xp = xrow + (c + 2) * KC;
            #pragma unroll
            for (int i = 0; i < 4; i++) xr[xb][i] = ((const float4*)xp)[i];
        }

        // ---- compute: two k16 steps ----
        #pragma unroll
        for (int ks = 0; ks < 2; ks++) {
            const uint32_t kb = (uint32_t)(ks * 32);
            uint32_t bh[8][2], bl[8][2];
            #pragma unroll
            for (int p = 0; p < 4; p++) {
                const uint32_t boff = (uint32_t)((p * 16 + b_nrow) * (XSTR * 2)) + kb + b_kb;
                ldsm4(bh[2 * p][0], bh[2 * p][1], bh[2 * p + 1][0], bh[2 * p + 1][1], whi_b + boff);
                ldsm4(bl[2 * p][0], bl[2 * p][1], bl[2 * p + 1][0], bl[2 * p + 1][1], wlo_b + boff);
            }
            uint32_t ah[4], al[4];
            const uint32_t aoff = (uint32_t)(a_row * (XSTR * 2)) + kb + a_kb;
            ldsm4(ah[0], ah[1], ah[2], ah[3], xhi_b + aoff);
            ldsm4(al[0], al[1], al[2], al[3], xlo_b + aoff);
            #pragma unroll
            for (int nt = 0; nt < 8; nt++) {
                mma16816(acc[nt], ah, bh[nt]);   // hi*hi
                mma16816(acc[nt], ah, bl[nt]);   // hi*lo
                mma16816(acc[nt], al, bh[nt]);   // lo*hi
            }
        }
    }

    // ---- fused epilogue: lane quad owns rows (wid*16+g) and (+8) ----------
    const int g = lane >> 2, t = lane & 3;
    #pragma unroll
    for (int j = 0; j < 2; j++) {
        const int row = m0 + wid * 16 + j * 8 + g;
        float v[16];
        #pragma unroll
        for (int nt = 0; nt < 8; nt++) {
            v[2 * nt]     = acc[nt][2 * j];
            v[2 * nt + 1] = acc[nt][2 * j + 1];
        }
        // logits write (cols nt*8 + 2t, +1)
        float* lp = logits + (size_t)row * NEXP;
        #pragma unroll
        for (int nt = 0; nt < 8; nt++)
            *(float2*)&lp[nt * 8 + 2 * t] = make_float2(v[2 * nt], v[2 * nt + 1]);

        // local top-3 (ascending col order, strict > -> lowest-index first)
        float b1 = -CUDART_INF_F, b2 = -CUDART_INF_F, b3 = -CUDART_INF_F;
        int i1 = 0, i2 = 0;
        #pragma unroll
        for (int q = 0; q < 16; q++) {
            const int col = (q >> 1) * 8 + 2 * t + (q & 1);
            const float val = v[q];
            if (val > b1)      { b3 = b2; b2 = b1; i2 = i1; b1 = val; i1 = col; }
            else if (val > b2) { b3 = b2; b2 = val; i2 = col; }
            else if (val > b3) { b3 = val; }
        }
        // quad merge (xor 1, then 2); 3rd is value-only (gap2 test)
        #pragma unroll
        for (int off = 1; off <= 2; off <<= 1) {
            const float ob1 = __shfl_xor_sync(0xffffffffu, b1, off);
            const int   oi1 = __shfl_xor_sync(0xffffffffu, i1, off);
            const float ob2 = __shfl_xor_sync(0xffffffffu, b2, off);
            const int   oi2 = __shfl_xor_sync(0xffffffffu, i2, off);
            const float ob3 = __shfl_xor_sync(0xffffffffu, b3, off);
            const bool afirst = (b1 > ob1) || (b1 == ob1 && i1 < oi1);
            const float w1 = afirst ? b1 : ob1;  const int wi1 = afirst ? i1 : oi1;
            const float a2v = afirst ? b2 : ob2; const int a2i = afirst ? i2 : oi2;
            const float a3v = afirst ? b3 : ob3;
            const float l1v = afirst ? ob1 : b1; const int l1i = afirst ? oi1 : i1;
            const float l2v = afirst ? ob2 : b2;
            const bool sfa = (a2v > l1v) || (a2v == l1v && a2i < l1i);
            b1 = w1; i1 = wi1;
            if (sfa) { b2 = a2v; i2 = a2i; b3 = fmaxf(a3v, l1v); }
            else     { b2 = l1v; i2 = l1i; b3 = fmaxf(a2v, l2v); }
        }

        // softmax (fp32, max-subtracted; deterministic fixed-order sums)
        float s = 0.f;
        #pragma unroll
        for (int q = 0; q < 16; q++) { v[q] = expf(v[q] - b1); s += v[q]; }
        s += __shfl_xor_sync(0xffffffffu, s, 1);
        s += __shfl_xor_sync(0xffffffffu, s, 2);
        const float inv = 1.f / s;
        float* ap = aff + (size_t)row * NEXP;
        #pragma unroll
        for (int nt = 0; nt < 8; nt++)
            *(float2*)&ap[nt * 8 + 2 * t] = make_float2(v[2 * nt] * inv, v[2 * nt + 1] * inv);

        if (t == 0) {
            idxf[2 * (size_t)row + 0] = (float)i1;
            idxf[2 * (size_t)row + 1] = (float)i2;
            if (b1 - b2 < TAU || b2 - b3 < TAU)
                g_ftok[atomicAdd(&g_nflag, 1)] = row;
        }
    }
}

// ---------------- exact fp32 top-2 for ambiguous tokens --------------------
// One block (256 thr, 8 warps) per flagged token. Warp w computes experts
// 8w..8w+7 CONCURRENTLY (8 accumulators, X loaded once per iteration -> 9
// independent loads in flight per lane). Thread 0 rescans all 64 exact logits
// (ascending, strict > -> lowest-index tie-break like jax.lax.top_k).
__global__ __launch_bounds__(256)
void refine_kernel(const float* __restrict__ X, const float* __restrict__ W,
                   float* __restrict__ idxf) {
    __shared__ float sl[NEXP];
    const int lane = threadIdx.x & 31, w = threadIdx.x >> 5;
    const int n = g_nflag;

    for (int tix = blockIdx.x; tix < n; tix += gridDim.x) {
        const int tok = g_ftok[tix];
        const float4* xp = (const float4*)(X + (size_t)tok * HDIM);
        float acc[8];
        #pragma unroll
        for (int e = 0; e < 8; e++) acc[e] = 0.f;

        #pragma unroll 4
        for (int k = lane; k < HDIM / 4; k += 32) {
            const float4 x = xp[k];
            #pragma unroll
            for (int e = 0; e < 8; e++) {
                const float4 b = ((const float4*)(W + (size_t)(w * 8 + e) * HDIM))[k];
                acc[e] = fmaf(x.x, b.x, fmaf(x.y, b.y, fmaf(x.z, b.z, fmaf(x.w, b.w, acc[e]))));
            }
        }
        #pragma unroll
        for (int e = 0; e < 8; e++) {
            float s = acc[e];
            #pragma unroll
            for (int off = 16; off; off >>= 1) s += __shfl_xor_sync(0xffffffffu, s, off);
            if (lane == 0) sl[w * 8 + e] = s;
        }
        __syncthreads();
        if (threadIdx.x == 0) {
            float b1 = -CUDART_INF_F, b2 = -CUDART_INF_F;
            int i1 = 0, i2 = 0;
            for (int e = 0; e < NEXP; e++) {
                const float vv = sl[e];
                if (vv > b1)      { b2 = b1; i2 = i1; b1 = vv; i1 = e; }
                else if (vv > b2) { b2 = vv; i2 = e; }
            }
            idxf[2 * (size_t)tok + 0] = (float)i1;
            idxf[2 * (size_t)tok + 1] = (float)i2;
        }
        __syncthreads();
    }
}

// ---------------------------------------------------------------------------
// d_out (fp32): [0,T*E) logits | [T*E,2TE) affinities | [2TE, 2TE+2T) indices
// ---------------------------------------------------------------------------
extern "C" void kernel_launch(void* const* d_in, const int* in_sizes, int n_in,
                              void* d_out, int out_size) {
    (void)in_sizes; (void)n_in; (void)out_size;
    const float* X = (const float*)d_in[0];
    const float* W = (const float*)d_in[1];
    float* out    = (float*)d_out;
    float* logits = out;
    float* aff    = out + (size_t)NTOK * NEXP;
    float* idxf   = out + 2 * (size_t)NTOK * NEXP;

    cudaFuncSetAttribute(router_gemm_kernel,
                         cudaFuncAttributeMaxDynamicSharedMemorySize, SM_TOTAL);

    wconv_kernel<<<(NEXP * HDIM + 255) / 256, 256>>>(W);
    router_gemm_kernel<<<NTOK / BM, 128, SM_TOTAL>>>(X, logits, aff, idxf);
    refine_kernel<<<512, 256>>>(X, W, idxf);
}

// round 10
// speedup vs baseline: 2.4167x; 1.4596x over previous
#include <cuda_runtime.h>
#include <cuda_bf16.h>
#include <cstdint>
#include <math_constants.h>

// Problem: T=16384 tokens (S=4096*B=4), H=2048, E=64, top_k=2
#define NTOK 16384
#define HDIM 2048
#define NEXP 64
#define BM   64               // tokens per CTA (2 CTAs/SM)
#define KC   32               // K elems per chunk (two mma k16 steps)
#define NCH  (HDIM / KC)      // 64 chunks
#define TAU  1.5e-4f          // top-k ambiguity margin (>> split error ~1e-6)

// ---- unified 4-stage smem ring: X fp32 + Whi/Wlo bf16 per stage ----------
#define XF      36                         // X row stride in floats (144B)
#define XROWB   (XF * 4)
#define WSTR    40                         // W row stride in bf16 (80B)
#define WROWB   (WSTR * 2)
#define STG_X   0
#define STG_WHI (BM * XROWB)               // 9216
#define STG_WLO (STG_WHI + NEXP * WROWB)   // 14336
#define STG_B   (STG_WLO + NEXP * WROWB)   // 19456 per stage
#define NSTG    4
#define SM_TOTAL (NSTG * STG_B)            // 77824

// W preconverted to bf16 hi/lo (512KB, device-global scratch)
__device__ __nv_bfloat16 g_whi[NEXP * HDIM];
__device__ __nv_bfloat16 g_wlo[NEXP * HDIM];
// ambiguous-token list for exact index refinement
__device__ int g_nflag;
__device__ int g_ftok[NTOK];

// ---------------- PTX helpers (base sm_100 / sm_80-era only) ---------------
__device__ __forceinline__ uint32_t smem_u32(const void* p) {
    uint32_t a;
    asm("{ .reg .u64 t; cvta.to.shared.u64 t, %1; cvt.u32.u64 %0, t; }" : "=r"(a) : "l"(p));
    return a;
}
__device__ __forceinline__ float2 lds64(uint32_t addr) {
    float2 v;
    asm volatile("ld.shared.v2.f32 {%0,%1}, [%2];" : "=f"(v.x), "=f"(v.y) : "r"(addr));
    return v;
}
__device__ __forceinline__ void ldsm4(uint32_t& r0, uint32_t& r1, uint32_t& r2, uint32_t& r3,
                                      uint32_t addr) {
    asm volatile("ldmatrix.sync.aligned.m8n8.x4.shared.b16 {%0,%1,%2,%3}, [%4];"
                 : "=r"(r0), "=r"(r1), "=r"(r2), "=r"(r3) : "r"(addr));
}
__device__ __forceinline__ void mma16816(float* c, const uint32_t* a, const uint32_t* b) {
    asm volatile(
        "mma.sync.aligned.m16n8k16.row.col.f32.bf16.bf16.f32 "
        "{%0,%1,%2,%3}, {%4,%5,%6,%7}, {%8,%9}, {%0,%1,%2,%3};"
        : "+f"(c[0]), "+f"(c[1]), "+f"(c[2]), "+f"(c[3])
        : "r"(a[0]), "r"(a[1]), "r"(a[2]), "r"(a[3]), "r"(b[0]), "r"(b[1]));
}
__device__ __forceinline__ void cp16(uint32_t saddr, const void* gaddr) {
    asm volatile("cp.async.ca.shared.global [%0], [%1], 16;" :: "r"(saddr), "l"(gaddr));
}
__device__ __forceinline__ void cp_commit() { asm volatile("cp.async.commit_group;"); }
__device__ __forceinline__ void cp_wait2()  { asm volatile("cp.async.wait_group 2;"); }
// pack {a,b} -> bf16x2 word with a in the LOW half
__device__ __forceinline__ uint32_t bfpack(float a, float b) {
    uint32_t r;
    asm("cvt.rn.bf16x2.f32 %0, %1, %2;" : "=r"(r) : "f"(b), "f"(a));
    return r;
}
__device__ __forceinline__ float bfround(float x) {
    return __bfloat162float(__float2bfloat16_rn(x));
}
// convert a float2 (consecutive k cols) into hi/lo bf16x2 words
__device__ __forceinline__ void cvt2(const float2 q, uint32_t& h, uint32_t& l) {
    h = bfpack(q.x, q.y);
    l = bfpack(q.x - bfround(q.x), q.y - bfround(q.y));
}

// --------------- W preconversion (+ flag counter reset) --------------------
__global__ void wconv_kernel(const float* __restrict__ W) {
    const int i = blockIdx.x * blockDim.x + threadIdx.x;
    if (i == 0) g_nflag = 0;
    if (i < NEXP * HDIM) {
        const float w  = W[i];
        const float hi = bfround(w);
        g_whi[i] = __float2bfloat16_rn(hi);
        g_wlo[i] = __float2bfloat16_rn(w - hi);
    }
}

// ------------------- fused GEMM + softmax + top-k kernel -------------------
// logits[T,64] = X[T,2048] . W[64,2048]^T, bf16 hi/lo split (3 products), fp32
// accum. 4 warps, warp = m16 x n64, BM=64 -> 2 CTAs/SM.
// X arrives in smem as RAW fp32 via cp.async (4-stage ring, no register
// staging); consumers read A-fragments with ld.shared.v2.f32 directly in mma
// fragment layout and convert hi/lo in-register (mapping identical to what
// ldmatrix.x4 produces, verified against the round-7 passing kernel).
// W rides the same ring preconverted to bf16, consumed via ldmatrix.
// One __syncthreads per chunk.
__global__ __launch_bounds__(128, 2)
void router_gemm_kernel(const float* __restrict__ X, float* __restrict__ logits,
                        float* __restrict__ aff, float* __restrict__ idxf) {
    extern __shared__ __align__(16) char smem[];
    const uint32_t sbase = smem_u32(smem);

    const int tid = threadIdx.x, wid = tid >> 5, lane = tid & 31;
    const int m0 = blockIdx.x * BM;

    // cp.async mapping (128 threads):
    //   X: row tid>>1 (0..63), 4x16B segments at half tid&1
    //   W: row tid>>1, 32B half tid&1 (2x cp16 each for hi and lo)
    const int crow = tid >> 1, chalf = tid & 1;
    const float* gx          = X + (size_t)(m0 + crow) * HDIM + chalf * 16;
    const __nv_bfloat16* gwh = g_whi + (size_t)crow * HDIM + chalf * 16;
    const __nv_bfloat16* gwl = g_wlo + (size_t)crow * HDIM + chalf * 16;
    const uint32_t x_dst = (uint32_t)(crow * XROWB + chalf * 64);
    const uint32_t w_dst = (uint32_t)(crow * WROWB + chalf * 32);

    #define ISSUE_STAGE(c) do {                                                \
        const uint32_t st_ = sbase + ((c) & 3) * STG_B;                         \
        const int ko = (c) * KC;                                                \
        cp16(st_ + STG_X + x_dst,        gx + ko);                              \
        cp16(st_ + STG_X + x_dst + 16,   gx + ko + 4);                          \
        cp16(st_ + STG_X + x_dst + 32,   gx + ko + 8);                          \
        cp16(st_ + STG_X + x_dst + 48,   gx + ko + 12);                         \
        cp16(st_ + STG_WHI + w_dst,      gwh + ko);                             \
        cp16(st_ + STG_WHI + w_dst + 16, gwh + ko + 8);                         \
        cp16(st_ + STG_WLO + w_dst,      gwl + ko);                             \
        cp16(st_ + STG_WLO + w_dst + 16, gwl + ko + 8);                         \
    } while (0)

    // prologue: chunks 0,1,2 in flight
    ISSUE_STAGE(0); cp_commit();
    ISSUE_STAGE(1); cp_commit();
    ISSUE_STAGE(2); cp_commit();

    float acc[8][4];
    #pragma unroll
    for (int nt = 0; nt < 8; nt++)
        #pragma unroll
        for (int q = 0; q < 4; q++) acc[nt][q] = 0.f;

    // fragment addressing
    const int r = lane >> 2, t = lane & 3;
    const int b_nrow = (lane & 7) + ((lane >> 4) & 1) * 8;
    const int b_kb   = ((lane >> 3) & 1) * 16;
    // A: lane reads rows (wid*16+r, +8), k-col pairs (2t, 8+2t) per k16 step
    const uint32_t a_base = (uint32_t)((wid * 16 + r) * XROWB + 2 * t * 4);

    #pragma unroll 1
    for (int c = 0; c < NCH; c++) {
        cp_wait2();          // chunk c resident (2 younger groups pending)
        __syncthreads();     // visibility + all warps done with chunk c-1

        if (c + 3 < NCH) ISSUE_STAGE(c + 3);
        cp_commit();         // constant-rate commits (empty at tail)

        const uint32_t st    = sbase + (c & 3) * STG_B;
        const uint32_t xs    = st + STG_X;
        const uint32_t whi_b = st + STG_WHI;
        const uint32_t wlo_b = st + STG_WLO;

        #pragma unroll
        for (int ks = 0; ks < 2; ks++) {
            // B fragments via ldmatrix (proven mapping)
            uint32_t bh[8][2], bl[8][2];
            #pragma unroll
            for (int p = 0; p < 4; p++) {
                const uint32_t boff = (uint32_t)((p * 16 + b_nrow) * WROWB) + ks * 32 + b_kb;
                ldsm4(bh[2 * p][0], bh[2 * p][1], bh[2 * p + 1][0], bh[2 * p + 1][1], whi_b + boff);
                ldsm4(bl[2 * p][0], bl[2 * p][1], bl[2 * p + 1][0], bl[2 * p + 1][1], wlo_b + boff);
            }
            // A fragments: direct shared loads (u32 addresses), convert in-reg
            const uint32_t ab = xs + a_base + (uint32_t)(ks * 64);
            const float2 q0 = lds64(ab);
            const float2 q1 = lds64(ab + 8 * XROWB);
            const float2 q2 = lds64(ab + 32);
            const float2 q3 = lds64(ab + 8 * XROWB + 32);
            uint32_t ah[4], al[4];
            cvt2(q0, ah[0], al[0]);   // (row r,   k 2t,2t+1)
            cvt2(q1, ah[1], al[1]);   // (row r+8, k 2t,2t+1)
            cvt2(q2, ah[2], al[2]);   // (row r,   k 8+2t,+1)
            cvt2(q3, ah[3], al[3]);   // (row r+8, k 8+2t,+1)
            #pragma unroll
            for (int nt = 0; nt < 8; nt++) {
                mma16816(acc[nt], ah, bh[nt]);   // hi*hi
                mma16816(acc[nt], ah, bl[nt]);   // hi*lo
                mma16816(acc[nt], al, bh[nt]);   // lo*hi
            }
        }
    }
    #undef ISSUE_STAGE

    // ---- fused epilogue: lane quad owns rows (wid*16+g) and (+8) ----------
    const int g = r;  // lane>>2
    #pragma unroll
    for (int j = 0; j < 2; j++) {
        const int row = m0 + wid * 16 + j * 8 + g;
        float v[16];
        #pragma unroll
        for (int nt = 0; nt < 8; nt++) {
            v[2 * nt]     = acc[nt][2 * j];
            v[2 * nt + 1] = acc[nt][2 * j + 1];
        }
        float* lp = logits + (size_t)row * NEXP;
        #pragma unroll
        for (int nt = 0; nt < 8; nt++)
            *(float2*)&lp[nt * 8 + 2 * t] = make_float2(v[2 * nt], v[2 * nt + 1]);

        // local top-3 (ascending col order, strict > -> lowest-index first)
        float b1 = -CUDART_INF_F, b2 = -CUDART_INF_F, b3 = -CUDART_INF_F;
        int i1 = 0, i2 = 0;
        #pragma unroll
        for (int q = 0; q < 16; q++) {
            const int col = (q >> 1) * 8 + 2 * t + (q & 1);
            const float val = v[q];
            if (val > b1)      { b3 = b2; b2 = b1; i2 = i1; b1 = val; i1 = col; }
            else if (val > b2) { b3 = b2; b2 = val; i2 = col; }
            else if (val > b3) { b3 = val; }
        }
        // quad merge (xor 1, then 2); 3rd best is value-only (gap2 test)
        #pragma unroll
        for (int off = 1; off <= 2; off <<= 1) {
            const float ob1 = __shfl_xor_sync(0xffffffffu, b1, off);
            const int   oi1 = __shfl_xor_sync(0xffffffffu, i1, off);
            const float ob2 = __shfl_xor_sync(0xffffffffu, b2, off);
            const int   oi2 = __shfl_xor_sync(0xffffffffu, i2, off);
            const float ob3 = __shfl_xor_sync(0xffffffffu, b3, off);
            const bool afirst = (b1 > ob1) || (b1 == ob1 && i1 < oi1);
            const float w1 = afirst ? b1 : ob1;  const int wi1 = afirst ? i1 : oi1;
            const float a2v = afirst ? b2 : ob2; const int a2i = afirst ? i2 : oi2;
            const float a3v = afirst ? b3 : ob3;
            const float l1v = afirst ? ob1 : b1; const int l1i = afirst ? oi1 : i1;
            const float l2v = afirst ? ob2 : b2;
            const bool sfa = (a2v > l1v) || (a2v == l1v && a2i < l1i);
            b1 = w1; i1 = wi1;
            if (sfa) { b2 = a2v; i2 = a2i; b3 = fmaxf(a3v, l1v); }
            else     { b2 = l1v; i2 = l1i; b3 = fmaxf(a2v, l2v); }
        }

        // softmax (fp32, max-subtracted; deterministic fixed-order sums)
        float s = 0.f;
        #pragma unroll
        for (int q = 0; q < 16; q++) { v[q] = expf(v[q] - b1); s += v[q]; }
        s += __shfl_xor_sync(0xffffffffu, s, 1);
        s += __shfl_xor_sync(0xffffffffu, s, 2);
        const float inv = 1.f / s;
        float* ap = aff + (size_t)row * NEXP;
        #pragma unroll
        for (int nt = 0; nt < 8; nt++)
            *(float2*)&ap[nt * 8 + 2 * t] = make_float2(v[2 * nt] * inv, v[2 * nt + 1] * inv);

        if (t == 0) {
            idxf[2 * (size_t)row + 0] = (float)i1;
            idxf[2 * (size_t)row + 1] = (float)i2;
            if (b1 - b2 < TAU || b2 - b3 < TAU)
                g_ftok[atomicAdd(&g_nflag, 1)] = row;
        }
    }
}

// ---------------- exact fp32 top-2 for ambiguous tokens --------------------
// One block (256 thr, 8 warps) per flagged token; warp w computes experts
// 8w..8w+7 concurrently (9 independent loads/lane in flight).
__global__ __launch_bounds__(256)
void refine_kernel(const float* __restrict__ X, const float* __restrict__ W,
                   float* __restrict__ idxf) {
    __shared__ float sl[NEXP];
    const int lane = threadIdx.x & 31, w = threadIdx.x >> 5;
    const int n = g_nflag;

    for (int tix = blockIdx.x; tix < n; tix += gridDim.x) {
        const int tok = g_ftok[tix];
        const float4* xp = (const float4*)(X + (size_t)tok * HDIM);
        float acc[8];
        #pragma unroll
        for (int e = 0; e < 8; e++) acc[e] = 0.f;

        #pragma unroll 4
        for (int k = lane; k < HDIM / 4; k += 32) {
            const float4 x = xp[k];
            #pragma unroll
            for (int e = 0; e < 8; e++) {
                const float4 b = ((const float4*)(W + (size_t)(w * 8 + e) * HDIM))[k];
                acc[e] = fmaf(x.x, b.x, fmaf(x.y, b.y, fmaf(x.z, b.z, fmaf(x.w, b.w, acc[e]))));
            }
        }
        #pragma unroll
        for (int e = 0; e < 8; e++) {
            float s = acc[e];
            #pragma unroll
            for (int off = 16; off; off >>= 1) s += __shfl_xor_sync(0xffffffffu, s, off);
            if (lane == 0) sl[w * 8 + e] = s;
        }
        __syncthreads();
        if (threadIdx.x == 0) {
            float b1 = -CUDART_INF_F, b2 = -CUDART_INF_F;
            int i1 = 0, i2 = 0;
            for (int e = 0; e < NEXP; e++) {
                const float vv = sl[e];
                if (vv > b1)      { b2 = b1; i2 = i1; b1 = vv; i1 = e; }
                else if (vv > b2) { b2 = vv; i2 = e; }
            }
            idxf[2 * (size_t)tok + 0] = (float)i1;
            idxf[2 * (size_t)tok + 1] = (float)i2;
        }
        __syncthreads();
    }
}

// ---------------------------------------------------------------------------
// d_out (fp32): [0,T*E) logits | [T*E,2TE) affinities | [2TE, 2TE+2T) indices
// ---------------------------------------------------------------------------
extern "C" void kernel_launch(void* const* d_in, const int* in_sizes, int n_in,
                              void* d_out, int out_size) {
    (void)in_sizes; (void)n_in; (void)out_size;
    const float* X = (const float*)d_in[0];
    const float* W = (const float*)d_in[1];
    float* out    = (float*)d_out;
    float* logits = out;
    float* aff    = out + (size_t)NTOK * NEXP;
    float* idxf   = out + 2 * (size_t)NTOK * NEXP;

    cudaFuncSetAttribute(router_gemm_kernel,
                         cudaFuncAttributeMaxDynamicSharedMemorySize, SM_TOTAL);

    wconv_kernel<<<(NEXP * HDIM + 255) / 256, 256>>>(W);
    router_gemm_kernel<<<NTOK / BM, 128, SM_TOTAL>>>(X, logits, aff, idxf);
    refine_kernel<<<512, 256>>>(X, W, idxf);
}

// round 11
// speedup vs baseline: 2.5778x; 1.0667x over previous
#include <cuda_runtime.h>
#include <cuda_bf16.h>
#include <cstdint>
#include <math_constants.h>

// Problem: T=16384 tokens (S=4096*B=4), H=2048, E=64, top_k=2
#define NTOK 16384
#define HDIM 2048
#define NEXP 64
#define BM   64               // tokens per CTA (2 CTAs/SM)
#define KC   32               // K elems per chunk (two k16 steps, split across warpgroups)
#define NCH  (HDIM / KC)      // 64 chunks
#define THREADS 256
#define TAU  1.5e-4f          // top-k ambiguity margin (>> split error ~1e-6)

// ---- unified 5-stage smem ring: X fp32 + Whi/Wlo bf16 per stage ----------
#define XF      36                         // X row stride in floats (144B, 16B-aligned)
#define XROWB   (XF * 4)
#define WSTR    40                         // W row stride in bf16 (80B, 16B-aligned)
#define WROWB   (WSTR * 2)
#define STG_X   0
#define STG_WHI (BM * XROWB)               // 9216
#define STG_WLO (STG_WHI + NEXP * WROWB)   // 14336
#define STG_B   (STG_WLO + NEXP * WROWB)   // 19456 per stage
#define NSTG    5
#define SM_TOTAL (NSTG * STG_B)            // 97280 (x2 CTAs = 194560 < 227KB)

// W preconverted to bf16 hi/lo (512KB, device-global scratch)
__device__ __nv_bfloat16 g_whi[NEXP * HDIM];
__device__ __nv_bfloat16 g_wlo[NEXP * HDIM];
// ambiguous-token list for exact index refinement
__device__ int g_nflag;
__device__ int g_ftok[NTOK];

// ---------------- PTX helpers (base sm_100 / sm_80-era only) ---------------
__device__ __forceinline__ uint32_t smem_u32(const void* p) {
    uint32_t a;
    asm("{ .reg .u64 t; cvta.to.shared.u64 t, %1; cvt.u32.u64 %0, t; }" : "=r"(a) : "l"(p));
    return a;
}
__device__ __forceinline__ float2 lds64(uint32_t addr) {
    float2 v;
    asm volatile("ld.shared.v2.f32 {%0,%1}, [%2];" : "=f"(v.x), "=f"(v.y) : "r"(addr));
    return v;
}
__device__ __forceinline__ float4 lds128f(uint32_t addr) {
    float4 v;
    asm volatile("ld.shared.v4.f32 {%0,%1,%2,%3}, [%4];"
                 : "=f"(v.x), "=f"(v.y), "=f"(v.z), "=f"(v.w) : "r"(addr));
    return v;
}
__device__ __forceinline__ void sts128f(uint32_t addr, float x, float y, float z, float w) {
    asm volatile("st.shared.v4.f32 [%0], {%1,%2,%3,%4};"
                 :: "r"(addr), "f"(x), "f"(y), "f"(z), "f"(w) : "memory");
}
__device__ __forceinline__ void ldsm4(uint32_t& r0, uint32_t& r1, uint32_t& r2, uint32_t& r3,
                                      uint32_t addr) {
    asm volatile("ldmatrix.sync.aligned.m8n8.x4.shared.b16 {%0,%1,%2,%3}, [%4];"
                 : "=r"(r0), "=r"(r1), "=r"(r2), "=r"(r3) : "r"(addr));
}
__device__ __forceinline__ void mma16816(float* c, const uint32_t* a, const uint32_t* b) {
    asm volatile(
        "mma.sync.aligned.m16n8k16.row.col.f32.bf16.bf16.f32 "
        "{%0,%1,%2,%3}, {%4,%5,%6,%7}, {%8,%9}, {%0,%1,%2,%3};"
        : "+f"(c[0]), "+f"(c[1]), "+f"(c[2]), "+f"(c[3])
        : "r"(a[0]), "r"(a[1]), "r"(a[2]), "r"(a[3]), "r"(b[0]), "r"(b[1]));
}
__device__ __forceinline__ void cp16(uint32_t saddr, const void* gaddr) {
    asm volatile("cp.async.ca.shared.global [%0], [%1], 16;" :: "r"(saddr), "l"(gaddr));
}
__device__ __forceinline__ void cp_commit() { asm volatile("cp.async.commit_group;"); }
__device__ __forceinline__ void cp_wait3()  { asm volatile("cp.async.wait_group 3;"); }
// pack {a,b} -> bf16x2 word with a in the LOW half
__device__ __forceinline__ uint32_t bfpack(float a, float b) {
    uint32_t r;
    asm("cvt.rn.bf16x2.f32 %0, %1, %2;" : "=r"(r) : "f"(b), "f"(a));
    return r;
}
__device__ __forceinline__ float bfround(float x) {
    return __bfloat162float(__float2bfloat16_rn(x));
}
__device__ __forceinline__ void cvt2(const float2 q, uint32_t& h, uint32_t& l) {
    h = bfpack(q.x, q.y);
    l = bfpack(q.x - bfround(q.x), q.y - bfround(q.y));
}

// --------------- W preconversion (+ flag counter reset) --------------------
__global__ void wconv_kernel(const float* __restrict__ W) {
    const int i = blockIdx.x * blockDim.x + threadIdx.x;
    if (i == 0) g_nflag = 0;
    if (i < NEXP * HDIM) {
        const float w  = W[i];
        const float hi = bfround(w);
        g_whi[i] = __float2bfloat16_rn(hi);
        g_wlo[i] = __float2bfloat16_rn(w - hi);
    }
}

// ------------------- fused GEMM + softmax + top-k kernel -------------------
// logits[T,64] = X[T,2048] . W[64,2048]^T, bf16 hi/lo split (3 products), fp32
// accum. 8 warps, K-SPLIT: warpgroup 0 (warps 0-3) consumes k16 step 0 of each
// chunk, warpgroup 1 (warps 4-7) step 1; both accumulate partials, reduced in
// smem after the mainloop. Warp m-tile = (wid&3)*16. 2 CTAs/SM -> 4 warps/SMSP.
// X rides the ring as RAW fp32 (cp.async, no register staging); A-fragments
// read via ld.shared.v2.f32 in mma layout and converted in-register. W rides
// preconverted bf16, consumed via ldmatrix. One __syncthreads per chunk.
__global__ __launch_bounds__(THREADS, 2)
void router_gemm_kernel(const float* __restrict__ X, float* __restrict__ logits,
                        float* __restrict__ aff, float* __restrict__ idxf) {
    extern __shared__ __align__(16) char smem[];
    const uint32_t sbase = smem_u32(smem);

    const int tid = threadIdx.x, wid = tid >> 5, lane = tid & 31;
    const int m0 = blockIdx.x * BM;

    // cp.async mapping (256 threads, 4x cp16 each):
    //   X: row tid>>2 (0..63), 32B seg (tid&3) -> 2 cp16
    //   W: row tid>>2, 16B seg (tid&3) for hi and lo -> 2 cp16
    const int crow = tid >> 2, cseg = tid & 3;
    const float* gx          = X + (size_t)(m0 + crow) * HDIM + cseg * 8;
    const __nv_bfloat16* gwh = g_whi + (size_t)crow * HDIM + cseg * 8;
    const __nv_bfloat16* gwl = g_wlo + (size_t)crow * HDIM + cseg * 8;
    const uint32_t x_dst = (uint32_t)(crow * XROWB + cseg * 32);
    const uint32_t w_dst = (uint32_t)(crow * WROWB + cseg * 16);

    #define ISSUE_STAGE(c) do {                                                \
        const uint32_t st_ = sbase + ((c) % NSTG) * STG_B;                      \
        const int ko = (c) * KC;                                                \
        cp16(st_ + STG_X + x_dst,        gx + ko);                              \
        cp16(st_ + STG_X + x_dst + 16,   gx + ko + 4);                          \
        cp16(st_ + STG_WHI + w_dst,      gwh + ko);                             \
        cp16(st_ + STG_WLO + w_dst,      gwl + ko);                             \
    } while (0)

    // prologue: chunks 0..3 in flight
    ISSUE_STAGE(0); cp_commit();
    ISSUE_STAGE(1); cp_commit();
    ISSUE_STAGE(2); cp_commit();
    ISSUE_STAGE(3); cp_commit();

    float acc[8][4];
    #pragma unroll
    for (int nt = 0; nt < 8; nt++)
        #pragma unroll
        for (int q = 0; q < 4; q++) acc[nt][q] = 0.f;

    // fragment addressing; ks = warpgroup (0 or 1), mtile = wid&3
    const int ks = wid >> 2, mtile = wid & 3;
    const int r = lane >> 2, t = lane & 3;
    const int b_nrow = (lane & 7) + ((lane >> 4) & 1) * 8;
    const int b_kb   = ((lane >> 3) & 1) * 16;
    const uint32_t a_base = (uint32_t)((mtile * 16 + r) * XROWB + 2 * t * 4 + ks * 64);
    const uint32_t b_base = (uint32_t)(ks * 32 + b_kb);

    #pragma unroll 1
    for (int c = 0; c < NCH; c++) {
        cp_wait3();          // chunk c resident (3 younger groups pending)
        __syncthreads();     // visibility + all warps done with chunk c-1

        if (c + 4 < NCH) ISSUE_STAGE(c + 4);
        cp_commit();         // constant-rate commits (empty at tail)

        const uint32_t st    = sbase + (c % NSTG) * STG_B;
        const uint32_t xs    = st + STG_X;
        const uint32_t whi_b = st + STG_WHI;
        const uint32_t wlo_b = st + STG_WLO;

        // B fragments via ldmatrix (proven mapping), this warpgroup's k16 step
        uint32_t bh[8][2], bl[8][2];
        #pragma unroll
        for (int p = 0; p < 4; p++) {
            const uint32_t boff = (uint32_t)((p * 16 + b_nrow) * WROWB) + b_base;
            ldsm4(bh[2 * p][0], bh[2 * p][1], bh[2 * p + 1][0], bh[2 * p + 1][1], whi_b + boff);
            ldsm4(bl[2 * p][0], bl[2 * p][1], bl[2 * p + 1][0], bl[2 * p + 1][1], wlo_b + boff);
        }
        // A fragments: direct shared loads, convert in-register
        const uint32_t ab = xs + a_base;
        const float2 q0 = lds64(ab);
        const float2 q1 = lds64(ab + 8 * XROWB);
        const float2 q2 = lds64(ab + 32);
        const float2 q3 = lds64(ab + 8 * XROWB + 32);
        uint32_t ah[4], al[4];
        cvt2(q0, ah[0], al[0]);   // (row r,   k 2t,2t+1)
        cvt2(q1, ah[1], al[1]);   // (row r+8, k 2t,2t+1)
        cvt2(q2, ah[2], al[2]);   // (row r,   k 8+2t,+1)
        cvt2(q3, ah[3], al[3]);   // (row r+8, k 8+2t,+1)
        #pragma unroll
        for (int nt = 0; nt < 8; nt++) {
            mma16816(acc[nt], ah, bh[nt]);   // hi*hi
            mma16816(acc[nt], ah, bl[nt]);   // hi*lo
            mma16816(acc[nt], al, bh[nt]);   // lo*hi
        }
    }
    #undef ISSUE_STAGE

    // ---- cross-warpgroup reduction: wg1 spills, wg0 adds ------------------
    // layout: float4 per (nt, mtile, lane): offset = ((nt*4 + mtile)*32 + lane)*16
    __syncthreads();   // ring dead; reuse smem
    if (ks == 1) {
        #pragma unroll
        for (int nt = 0; nt < 8; nt++)
            sts128f(sbase + (uint32_t)(((nt * 4 + mtile) * 32 + lane) * 16),
                    acc[nt][0], acc[nt][1], acc[nt][2], acc[nt][3]);
    }
    __syncthreads();
    if (ks == 1) return;   // wg0 handles the epilogue
    #pragma unroll
    for (int nt = 0; nt < 8; nt++) {
        const float4 p = lds128f(sbase + (uint32_t)(((nt * 4 + mtile) * 32 + lane) * 16));
        acc[nt][0] += p.x; acc[nt][1] += p.y; acc[nt][2] += p.z; acc[nt][3] += p.w;
    }

    // ---- fused epilogue: lane quad owns rows (mtile*16+g) and (+8) --------
    const int g = r;
    #pragma unroll
    for (int j = 0; j < 2; j++) {
        const int row = m0 + mtile * 16 + j * 8 + g;
        float v[16];
        #pragma unroll
        for (int nt = 0; nt < 8; nt++) {
            v[2 * nt]     = acc[nt][2 * j];
            v[2 * nt + 1] = acc[nt][2 * j + 1];
        }
        float* lp = logits + (size_t)row * NEXP;
        #pragma unroll
        for (int nt = 0; nt < 8; nt++)
            *(float2*)&lp[nt * 8 + 2 * t] = make_float2(v[2 * nt], v[2 * nt + 1]);

        // local top-3 (ascending col order, strict > -> lowest-index first)
        float b1 = -CUDART_INF_F, b2 = -CUDART_INF_F, b3 = -CUDART_INF_F;
        int i1 = 0, i2 = 0;
        #pragma unroll
        for (int q = 0; q < 16; q++) {
            const int col = (q >> 1) * 8 + 2 * t + (q & 1);
            const float val = v[q];
            if (val > b1)      { b3 = b2; b2 = b1; i2 = i1; b1 = val; i1 = col; }
            else if (val > b2) { b3 = b2; b2 = val; i2 = col; }
            else if (val > b3) { b3 = val; }
        }
        // quad merge (xor 1, then 2); 3rd best is value-only (gap2 test)
        #pragma unroll
        for (int off = 1; off <= 2; off <<= 1) {
            const float ob1 = __shfl_xor_sync(0xffffffffu, b1, off);
            const int   oi1 = __shfl_xor_sync(0xffffffffu, i1, off);
            const float ob2 = __shfl_xor_sync(0xffffffffu, b2, off);
            const int   oi2 = __shfl_xor_sync(0xffffffffu, i2, off);
            const float ob3 = __shfl_xor_sync(0xffffffffu, b3, off);
            const bool afirst = (b1 > ob1) || (b1 == ob1 && i1 < oi1);
            const float w1 = afirst ? b1 : ob1;  const int wi1 = afirst ? i1 : oi1;
            const float a2v = afirst ? b2 : ob2; const int a2i = afirst ? i2 : oi2;
            const float a3v = afirst ? b3 : ob3;
            const float l1v = afirst ? ob1 : b1; const int l1i = afirst ? oi1 : i1;
            const float l2v = afirst ? ob2 : b2;
            const bool sfa = (a2v > l1v) || (a2v == l1v && a2i < l1i);
            b1 = w1; i1 = wi1;
            if (sfa) { b2 = a2v; i2 = a2i; b3 = fmaxf(a3v, l1v); }
            else     { b2 = l1v; i2 = l1i; b3 = fmaxf(a2v, l2v); }
        }

        // softmax (fp32, max-subtracted; deterministic fixed-order sums)
        float s = 0.f;
        #pragma unroll
        for (int q = 0; q < 16; q++) { v[q] = expf(v[q] - b1); s += v[q]; }
        s += __shfl_xor_sync(0xffffffffu, s, 1);
        s += __shfl_xor_sync(0xffffffffu, s, 2);
        const float inv = 1.f / s;
        float* ap = aff + (size_t)row * NEXP;
        #pragma unroll
        for (int nt = 0; nt < 8; nt++)
            *(float2*)&ap[nt * 8 + 2 * t] = make_float2(v[2 * nt] * inv, v[2 * nt + 1] * inv);

        if (t == 0) {
            idxf[2 * (size_t)row + 0] = (float)i1;
            idxf[2 * (size_t)row + 1] = (float)i2;
            if (b1 - b2 < TAU || b2 - b3 < TAU)
                g_ftok[atomicAdd(&g_nflag, 1)] = row;
        }
    }
}

// ---------------- exact fp32 top-2 for ambiguous tokens --------------------
// One block (256 thr, 8 warps) per flagged token; warp w computes experts
// 8w..8w+7 concurrently (9 independent loads/lane in flight).
__global__ __launch_bounds__(256)
void refine_kernel(const float* __restrict__ X, const float* __restrict__ W,
                   float* __restrict__ idxf) {
    __shared__ float sl[NEXP];
    const int lane = threadIdx.x & 31, w = threadIdx.x >> 5;
    const int n = g_nflag;

    for (int tix = blockIdx.x; tix < n; tix += gridDim.x) {
        const int tok = g_ftok[tix];
        const float4* xp = (const float4*)(X + (size_t)tok * HDIM);
        float acc[8];
        #pragma unroll
        for (int e = 0; e < 8; e++) acc[e] = 0.f;

        #pragma unroll 4
        for (int k = lane; k < HDIM / 4; k += 32) {
            const float4 x = xp[k];
            #pragma unroll
            for (int e = 0; e < 8; e++) {
                const float4 b = ((const float4*)(W + (size_t)(w * 8 + e) * HDIM))[k];
                acc[e] = fmaf(x.x, b.x, fmaf(x.y, b.y, fmaf(x.z, b.z, fmaf(x.w, b.w, acc[e]))));
            }
        }
        #pragma unroll
        for (int e = 0; e < 8; e++) {
            float s = acc[e];
            #pragma unroll
            for (int off = 16; off; off >>= 1) s += __shfl_xor_sync(0xffffffffu, s, off);
            if (lane == 0) sl[w * 8 + e] = s;
        }
        __syncthreads();
        if (threadIdx.x == 0) {
            float b1 = -CUDART_INF_F, b2 = -CUDART_INF_F;
            int i1 = 0, i2 = 0;
            for (int e = 0; e < NEXP; e++) {
                const float vv = sl[e];
                if (vv > b1)      { b2 = b1; i2 = i1; b1 = vv; i1 = e; }
                else if (vv > b2) { b2 = vv; i2 = e; }
            }
            idxf[2 * (size_t)tok + 0] = (float)i1;
            idxf[2 * (size_t)tok + 1] = (float)i2;
        }
        __syncthreads();
    }
}

// ---------------------------------------------------------------------------
// d_out (fp32): [0,T*E) logits | [T*E,2TE) affinities | [2TE, 2TE+2T) indices
// ---------------------------------------------------------------------------
extern "C" void kernel_launch(void* const* d_in, const int* in_sizes, int n_in,
                              void* d_out, int out_size) {
    (void)in_sizes; (void)n_in; (void)out_size;
    const float* X = (const float*)d_in[0];
    const float* W = (const float*)d_in[1];
    float* out    = (float*)d_out;
    float* logits = out;
    float* aff    = out + (size_t)NTOK * NEXP;
    float* idxf   = out + 2 * (size_t)NTOK * NEXP;

    cudaFuncSetAttribute(router_gemm_kernel,
                         cudaFuncAttributeMaxDynamicSharedMemorySize, SM_TOTAL);

    wconv_kernel<<<(NEXP * HDIM + 255) / 256, 256>>>(W);
    router_gemm_kernel<<<NTOK / BM, THREADS, SM_TOTAL>>>(X, logits, aff, idxf);
    refine_kernel<<<512, 256>>>(X, W, idxf);
}